// round 16
// baseline (speedup 1.0000x reference)
#include <cuda_runtime.h>
#include <cstdint>

// Problem constants
#define BATCH 32
#define TT 512
#define NINP 128
#define NHID 1024
#define KTOT 1152
#define DT_C 0.042f
#define EPSH 512.0f               // HARMONIC = N_HID * 0.5

// Geometry: 256 CTAs = 64 col-groups x 4 batch-groups, 256 threads (8 warps).
// 2 CTAs co-resident per SM -> two independent chains hide each other's latency.
#define NCTA 256
#define NCG  64
#define COLS 16
#define BPC  8
#define TPB  256
#define NW   8
#define KSL  144                  // k-rows per warp

#define BTH (BATCH * TT * NHID)

// SMEM (floats)
#define OFF_W   0
#define SZ_W    (KTOT * COLS)     // 18432 floats (73728 B), packed [k/2][c][k&1]
#define OFF_IN  (OFF_W + SZ_W)
#define SZ_IN   (KTOT * BPC)      // 9216 ([k][8b])
#define OFF_RED (OFF_IN + SZ_IN)
#define SZ_RED  (NW * 128)        // 1024 ([w][c*8+b])
#define SMEM_FLOATS (OFF_RED + SZ_RED)
#define SMEM_BYTES  (SMEM_FLOATS * 4)   // 114688 B -> 2 CTAs/SM

// ---- device scratch ----
__device__ float g_xT2[4 * TT * NINP * BPC];   // [bg][t][i][8b]
__device__ float g_hyT2[2][4][NHID * BPC];     // [parity][bg][h][8b]
// one 128B line per flag
__device__ __align__(128) unsigned g_flags[4][NCG][32];

typedef unsigned long long ull;

__device__ __forceinline__ void ffma2(ull& acc, ull a, ull b) {
    asm("fma.rn.f32x2 %0, %1, %2, %0;" : "+l"(acc) : "l"(a), "l"(b));
}
__device__ __forceinline__ ull add2(ull a, ull b) {
    ull r; asm("add.rn.f32x2 %0, %1, %2;" : "=l"(r) : "l"(a), "l"(b)); return r;
}
__device__ __forceinline__ ull pack2(float lo, float hi) {
    ull r; asm("mov.b64 %0, {%1, %2};" : "=l"(r) : "f"(lo), "f"(hi)); return r;
}
__device__ __forceinline__ unsigned ld_acq(const unsigned* p) {
    unsigned v;
    asm volatile("ld.global.acquire.gpu.u32 %0, [%1];" : "=r"(v) : "l"(p));
    return v;
}
__device__ __forceinline__ void st_rel(unsigned* p, unsigned v) {
    asm volatile("st.global.release.gpu.u32 [%0], %1;" :: "l"(p), "r"(v));
}

// ------------------------------------------------------------------
__global__ void k_init() {
    int idx = blockIdx.x * blockDim.x + threadIdx.x;
    int stride = gridDim.x * blockDim.x;
    for (int i = idx; i < 4 * NCG * 32; i += stride)
        (&g_flags[0][0][0])[i] = 0;
    for (int i = idx; i < 4 * NHID * BPC; i += stride)
        g_hyT2[0][0][i] = 0.0f;
}

__global__ void k_zero(float* __restrict__ p, int n4) {
    int idx = blockIdx.x * blockDim.x + threadIdx.x;
    int stride = gridDim.x * blockDim.x;
    float4 z = make_float4(0.f, 0.f, 0.f, 0.f);
    float4* p4 = reinterpret_cast<float4*>(p);
    for (int i = idx; i < n4; i += stride) p4[i] = z;
}

// x[b][t][i] -> g_xT2[bg][t][i][b&7]
__global__ void k_xpose(const float* __restrict__ x) {
    int idx = blockIdx.x * blockDim.x + threadIdx.x;
    int stride = gridDim.x * blockDim.x;
    const int N = 4 * TT * NINP * BPC;
    for (int o = idx; o < N; o += stride) {
        int blo = o & 7;
        int i = (o >> 3) & (NINP - 1);
        int t = (o >> 10) & (TT - 1);
        int bg = o >> 19;
        g_xT2[o] = x[((size_t)(bg * 8 + blo) * TT + t) * NINP + i];
    }
}

// ------------------------------------------------------------------
// persistent recurrent kernel: 256 CTAs x 256 threads, 2 CTAs/SM.
// GEMM lane = 2c + kp: c = col (0..15), kp = k-parity. Lane covers
// col c x 8 batches for rows {4ch+2kp, 4ch+2kp+1}; cross-kp shfl sum.
// ------------------------------------------------------------------
__global__ void __launch_bounds__(TPB, 2) k_recur(
    const float* __restrict__ x2h,
    const float* __restrict__ h2h,
    const float* __restrict__ gamma,
    const float* __restrict__ eps,
    const float* __restrict__ bias,
    float* __restrict__ out)
{
    extern __shared__ float sm[];
    float* w_s  = sm + OFF_W;     // packed [k/2][c][k&1]
    float* in_s = sm + OFF_IN;    // [k][8b]
    float* red  = sm + OFF_RED;   // [w][c*8+b]

    const int tid  = threadIdx.x;
    const int wid  = tid >> 5;
    const int lane = tid & 31;
    const int c    = lane >> 1;   // 0..15
    const int kp   = lane & 1;    // 0..1
    const int cgrp = blockIdx.x >> 2;
    const int bg   = blockIdx.x & 3;
    const int cg0  = cgrp * COLS;
    const int kb   = wid * KSL;

    // --- weights: coalesced global read -> packed SMEM [k/2][c][k&1] ---
    for (int idx = tid; idx < KTOT * COLS; idx += TPB) {
        int k = idx >> 4;
        int cc = idx & 15;
        float v = (k < NINP) ? x2h[(size_t)k * NHID + cg0 + cc]
                             : h2h[(size_t)(k - NINP) * NHID + cg0 + cc];
        w_s[((k >> 1) << 5) + (cc << 1) + (k & 1)] = v;
    }

    // --- update params (tid<128: uc=tid>>3, ub=tid&7) ---
    const int uc = tid >> 3;
    const int ub = tid & 7;
    const int hg = cg0 + uc;
    float hy_r = 0.f, hz_r = 0.f;
    float gam = 0.f, epc = 0.f, bi = 0.f;
    if (tid < 128) {
        gam = gamma[hg];
        epc = eps[hg] * EPSH;
        bi  = bias[hg];
    }

    // --- this warp's producer flags (hy rows [kb-128, kb+144-128)) ---
    int p0 = 0, npf = 0;
    {
        int ke = kb + KSL;
        if (ke > NINP) {
            int h0 = ((kb > NINP) ? kb : NINP) - NINP;
            int h1 = ke - NINP - 1;
            p0 = h0 >> 4;                 // 16 cols per producer CTA
            npf = (h1 >> 4) - p0 + 1;     // <= 9
        }
    }
    const unsigned* myflag = &g_flags[bg][p0 + lane][0];  // lanes 0..npf-1

    const float4* xs_all = (const float4*)(g_xT2 + (size_t)bg * (TT * NINP * BPC));
    const float2* wp2 = (const float2*)w_s + ((kb >> 1) << 4) + (kp << 4) + c;
    const ulonglong2* hq = (const ulonglong2*)in_s + ((kb + 2 * kp) << 1);
    float4* dst4 = (float4*)in_s;

    __syncthreads();

    for (int t = 0; t < TT; t++) {
        const int p = t & 1;

        // ---- stage x rows (no cross-CTA dependency; in_s warp-private) ----
        {
            const float4* xs = xs_all + (size_t)t * (NINP * BPC / 4);
#pragma unroll
            for (int i = lane; i < KSL * 2; i += 32) {
                int f4 = kb * 2 + i;
                if (f4 < NINP * 2) dst4[f4] = __ldg(xs + f4);
            }
        }

        // ---- fine-grained poll: only this warp's producers ----
        if (lane < npf) {
            const unsigned want = (unsigned)t;
            while (ld_acq(myflag) < want) { }
        }
        __syncwarp();

        // ---- stage hy rows (L2, cross-CTA coherent) ----
        {
            const float4* hy4 = (const float4*)(&g_hyT2[p][bg][0]);
#pragma unroll
            for (int i = lane; i < KSL * 2; i += 32) {
                int f4 = kb * 2 + i;
                if (f4 >= NINP * 2) dst4[f4] = __ldcg(hy4 + (f4 - NINP * 2));
            }
        }
        __syncwarp();

        // ---- GEMM: 36 fixed chunks; lane: col c, rows 4ch+2kp..+1, 8 b ----
        ull A0 = 0, A1 = 0, A2 = 0, A3 = 0;
#pragma unroll
        for (int ch = 0; ch < KSL / 4; ch++) {
            float2 wv = wp2[ch * 32];              // w[r0][c], w[r1][c] dense
            ulonglong2 ha = hq[ch * 8 + 0];        // row r0, b0..3
            ulonglong2 hb = hq[ch * 8 + 1];        // row r0, b4..7
            ulonglong2 hc = hq[ch * 8 + 2];        // row r1, b0..3
            ulonglong2 hd = hq[ch * 8 + 3];        // row r1, b4..7
            ull w20 = pack2(wv.x, wv.x);
            ffma2(A0, w20, ha.x); ffma2(A1, w20, ha.y);
            ffma2(A2, w20, hb.x); ffma2(A3, w20, hb.y);
            ull w21 = pack2(wv.y, wv.y);
            ffma2(A0, w21, hc.x); ffma2(A1, w21, hc.y);
            ffma2(A2, w21, hd.x); ffma2(A3, w21, hd.y);
        }

        // ---- cross-kp reduction (lane pairs 2c / 2c+1) ----
        A0 = add2(A0, __shfl_xor_sync(0xffffffffu, A0, 1));
        A1 = add2(A1, __shfl_xor_sync(0xffffffffu, A1, 1));
        A2 = add2(A2, __shfl_xor_sync(0xffffffffu, A2, 1));
        A3 = add2(A3, __shfl_xor_sync(0xffffffffu, A3, 1));

        // ---- red store: even lanes store col c (8 batches) ----
        if (kp == 0) {
            ulonglong2* rp = (ulonglong2*)(red + (wid << 7) + (c << 3));
            rp[0] = make_ulonglong2(A0, A1);
            rp[1] = make_ulonglong2(A2, A3);
        }
        __syncthreads();   // CTA has observed ALL 64 flags >= t by here

        // ---- update: tid<128, (c=tid>>3, b=tid&7), coalesced red reads ----
        if (tid < 128) {
            float pre = bi;
#pragma unroll
            for (int w = 0; w < NW; w++)
                pre += red[(w << 7) + tid];
            float drive = tanhf(pre);
            hz_r += DT_C * (drive - gam * hy_r - epc * hz_r);
            hy_r += DT_C * hz_r;

            __stcg(&g_hyT2[p ^ 1][bg][hg * BPC + ub], hy_r);  // 512B coalesced
        }
        __syncthreads();

        // ---- single-fence release to this CTA's private flag line ----
        if (tid == 0) {
            __threadfence();
            st_rel(&g_flags[bg][cgrp][0], (unsigned)(t + 1));
        }

        // out stores off the inter-CTA critical path
        if (tid < 128) {
            const size_t obase = (size_t)(bg * 8 + ub) * (TT * NHID)
                               + (size_t)t * NHID + hg;
            out[obase]       = hy_r;
            out[obase + BTH] = hz_r;
        }
    }
}

// ------------------------------------------------------------------
extern "C" void kernel_launch(void* const* d_in, const int* in_sizes, int n_in,
                              void* d_out, int out_size) {
    const float* x     = (const float*)d_in[0];
    const float* x2h   = (const float*)d_in[1];
    const float* h2h   = (const float*)d_in[2];
    const float* gamma = (const float*)d_in[3];
    const float* eps   = (const float*)d_in[4];
    const float* bias  = (const float*)d_in[5];
    float* out = (float*)d_out;

    cudaFuncSetAttribute(k_recur, cudaFuncAttributeMaxDynamicSharedMemorySize, SMEM_BYTES);

    k_init<<<64, 256>>>();
    k_xpose<<<512, 256>>>(x);
    // u and spike outputs are identically zero (u never leaves 0)
    k_zero<<<2048, 256>>>(out + (size_t)2 * BTH, (2 * BTH) / 4);
    k_recur<<<NCTA, TPB, SMEM_BYTES>>>(x2h, h2h, gamma, eps, bias, out);
}